// round 1
// baseline (speedup 1.0000x reference)
#include <cuda_runtime.h>

// SSIM loss, fused single-pass tiled kernel + tiny finish reduction.
// Separable 11-tap Gaussian (sigma=1.5), weights baked as immediates so
// ptxas emits FFMA R,R,IMM,R (rt_SMSP=1 -> full 128 FMA/cyc/SM).

#define TX 32
#define TY 32
#define HALO 5
#define IN_W 42            // TX + 2*HALO
#define IN_H 42
#define SP_STRIDE 45       // odd & !=1 mod pattern -> conflict-free H-pass reads
#define H_STRIDE 33        // lane x -> bank x for V-pass
#define NTHREADS 256
#define IMG 512
#define TILES_X 16
#define TILES_Y 16
#define PLANES 48          // 16 batch * 3 channels
#define NBLOCKS (PLANES * TILES_Y * TILES_X)   // 12288
#define NPIX 12582912.0f   // 16*3*512*512

#define C1 1.0e-4f
#define C2 9.0e-4f

__device__ float g_partials[NBLOCKS];

// Normalized 1D Gaussian weights for window=11, sigma=1.5
__device__ __forceinline__ constexpr float Wt(int k) {
    constexpr float w[11] = {
        0.00102838f, 0.00759877f, 0.03600081f, 0.10936072f, 0.21300553f,
        0.26601169f,
        0.21300553f, 0.10936072f, 0.03600081f, 0.00759877f, 0.00102838f
    };
    return w[k];
}

__global__ __launch_bounds__(NTHREADS)
void ssim_tile_kernel(const float* __restrict__ pred,
                      const float* __restrict__ targ) {
    __shared__ float s_p[IN_H * SP_STRIDE];
    __shared__ float s_t[IN_H * SP_STRIDE];
    __shared__ float s_H[5 * IN_H * H_STRIDE];
    __shared__ float s_warp[8];

    const int tid = threadIdx.x;
    const int ox = blockIdx.x * TX;
    const int oy = blockIdx.y * TY;
    const long plane_base = (long)blockIdx.z * (IMG * IMG);
    const float* __restrict__ p_plane = pred + plane_base;
    const float* __restrict__ t_plane = targ + plane_base;

    // ---- Phase 0: load halo tile (zero padding outside image) ----
    #pragma unroll 2
    for (int i = tid; i < IN_H * IN_W; i += NTHREADS) {
        int r = i / IN_W;
        int c = i - r * IN_W;
        int gy = oy + r - HALO;
        int gx = ox + c - HALO;
        float pv = 0.0f, tv = 0.0f;
        if ((unsigned)gy < IMG && (unsigned)gx < IMG) {
            int gi = gy * IMG + gx;
            pv = p_plane[gi];
            tv = t_plane[gi];
        }
        s_p[r * SP_STRIDE + c] = pv;
        s_t[r * SP_STRIDE + c] = tv;
    }
    __syncthreads();

    // ---- Phase 1: horizontal blur of 5 fields into s_H ----
    // 42 rows x 8 column-groups (4 outputs each) = 336 tasks
    for (int task = tid; task < IN_H * 8; task += NTHREADS) {
        int r = task >> 3;
        int c0 = (task & 7) * 4;
        const float* prow = &s_p[r * SP_STRIDE + c0];
        const float* trow = &s_t[r * SP_STRIDE + c0];

        float wp[14], wt[14], pp[14], tt[14], pt[14];
        #pragma unroll
        for (int i = 0; i < 14; i++) {
            float a = prow[i];
            float b = trow[i];
            wp[i] = a; wt[i] = b;
            pp[i] = a * a; tt[i] = b * b; pt[i] = a * b;
        }
        #pragma unroll
        for (int j = 0; j < 4; j++) {
            float a0 = 0.f, a1 = 0.f, a2 = 0.f, a3 = 0.f, a4 = 0.f;
            #pragma unroll
            for (int k = 0; k < 11; k++) {
                a0 = fmaf(Wt(k), wp[j + k], a0);
                a1 = fmaf(Wt(k), wt[j + k], a1);
                a2 = fmaf(Wt(k), pp[j + k], a2);
                a3 = fmaf(Wt(k), tt[j + k], a3);
                a4 = fmaf(Wt(k), pt[j + k], a4);
            }
            int hc = r * H_STRIDE + c0 + j;
            s_H[0 * IN_H * H_STRIDE + hc] = a0;
            s_H[1 * IN_H * H_STRIDE + hc] = a1;
            s_H[2 * IN_H * H_STRIDE + hc] = a2;
            s_H[3 * IN_H * H_STRIDE + hc] = a3;
            s_H[4 * IN_H * H_STRIDE + hc] = a4;
        }
    }
    __syncthreads();

    // ---- Phase 2: vertical blur + SSIM, 4 output rows per thread ----
    const int x = tid & 31;
    const int y0 = (tid >> 5) * 4;

    float acc[5][4];
    #pragma unroll
    for (int f = 0; f < 5; f++) {
        float h[14];
        #pragma unroll
        for (int i = 0; i < 14; i++)
            h[i] = s_H[(f * IN_H + y0 + i) * H_STRIDE + x];
        #pragma unroll
        for (int j = 0; j < 4; j++) {
            float a = 0.f;
            #pragma unroll
            for (int k = 0; k < 11; k++)
                a = fmaf(Wt(k), h[j + k], a);
            acc[f][j] = a;
        }
    }

    float local = 0.0f;
    #pragma unroll
    for (int j = 0; j < 4; j++) {
        float mu_p = acc[0][j], mu_t = acc[1][j];
        float spp = acc[2][j], stt = acc[3][j], spt = acc[4][j];
        float mu_p2 = mu_p * mu_p;
        float mu_t2 = mu_t * mu_t;
        float mu_pt = mu_p * mu_t;
        float num = (2.0f * mu_pt + C1) * (2.0f * (spt - mu_pt) + C2);
        float den = (mu_p2 + mu_t2 + C1) * ((spp - mu_p2) + (stt - mu_t2) + C2);
        local += num / den;
    }

    // ---- Phase 3: block reduction (deterministic), one partial per block ----
    float v = local;
    #pragma unroll
    for (int off = 16; off; off >>= 1)
        v += __shfl_xor_sync(0xFFFFFFFFu, v, off);
    if ((tid & 31) == 0) s_warp[tid >> 5] = v;
    __syncthreads();
    if (tid < 8) {
        v = s_warp[tid];
        #pragma unroll
        for (int off = 4; off; off >>= 1)
            v += __shfl_xor_sync(0x000000FFu, v, off);
        if (tid == 0) {
            int bl = (blockIdx.z * TILES_Y + blockIdx.y) * TILES_X + blockIdx.x;
            g_partials[bl] = v;
        }
    }
}

__global__ void finish_kernel(float* __restrict__ out) {
    __shared__ float ws[32];
    int tid = threadIdx.x;
    float s = 0.0f;
    for (int i = tid; i < NBLOCKS; i += 1024)
        s += g_partials[i];
    #pragma unroll
    for (int off = 16; off; off >>= 1)
        s += __shfl_xor_sync(0xFFFFFFFFu, s, off);
    if ((tid & 31) == 0) ws[tid >> 5] = s;
    __syncthreads();
    if (tid < 32) {
        s = ws[tid];
        #pragma unroll
        for (int off = 16; off; off >>= 1)
            s += __shfl_xor_sync(0xFFFFFFFFu, s, off);
        if (tid == 0) out[0] = 1.0f - s * (1.0f / NPIX);
    }
}

extern "C" void kernel_launch(void* const* d_in, const int* in_sizes, int n_in,
                              void* d_out, int out_size) {
    const float* pred = (const float*)d_in[0];
    const float* targ = (const float*)d_in[1];
    float* out = (float*)d_out;

    dim3 grid(TILES_X, TILES_Y, PLANES);
    ssim_tile_kernel<<<grid, NTHREADS>>>(pred, targ);
    finish_kernel<<<1, 1024>>>(out);
}

// round 2
// speedup vs baseline: 1.0343x; 1.0343x over previous
#include <cuda_runtime.h>

// SSIM loss — fused separable Gaussian blur + SSIM + device-wide reduction.
// R2: f32x2 packed FMA chains (sm_10x), fast division, ticket-fused reduction.

typedef unsigned long long u64;

#define TX 32
#define TY 32
#define HALO 5
#define IN_W 42            // TX + 2*HALO
#define IN_H 42
#define SP_STRIDE 45
#define H_STRIDE 33
#define NTHREADS 256
#define IMG 512
#define TILES_X 16
#define TILES_Y 16
#define PLANES 48
#define NBLOCKS (PLANES * TILES_Y * TILES_X)   // 12288
#define NPIX 12582912.0f

#define C1 1.0e-4f
#define C2 9.0e-4f

__device__ float g_partials[NBLOCKS];
__device__ unsigned g_ticket = 0;

// Normalized 1D Gaussian weights, window=11, sigma=1.5
__device__ __forceinline__ constexpr float Wt(int k) {
    constexpr float w[11] = {
        0.00102838f, 0.00759877f, 0.03600081f, 0.10936072f, 0.21300553f,
        0.26601169f,
        0.21300553f, 0.10936072f, 0.03600081f, 0.00759877f, 0.00102838f
    };
    return w[k];
}

// ---- f32x2 packed helpers (Blackwell sm_10x) ----
__device__ __forceinline__ u64 pk(float lo, float hi) {
    u64 r;
    asm("mov.b64 %0, {%1, %2};" : "=l"(r) : "f"(lo), "f"(hi));
    return r;
}
__device__ __forceinline__ float2 upk(u64 v) {
    float2 r;
    asm("mov.b64 {%0, %1}, %2;" : "=f"(r.x), "=f"(r.y) : "l"(v));
    return r;
}
__device__ __forceinline__ u64 fma2(u64 a, u64 b, u64 c) {
    u64 d;
    asm("fma.rn.f32x2 %0, %1, %2, %3;" : "=l"(d) : "l"(a), "l"(b), "l"(c));
    return d;
}

__global__ __launch_bounds__(NTHREADS)
void ssim_tile_kernel(const float* __restrict__ pred,
                      const float* __restrict__ targ,
                      float* __restrict__ out) {
    __shared__ float s_p[IN_H * SP_STRIDE];
    __shared__ float s_t[IN_H * SP_STRIDE];
    __shared__ float2 s_Hmu[IN_H * H_STRIDE];   // (mu_p, mu_t) H-blurred
    __shared__ float2 s_Hsq[IN_H * H_STRIDE];   // (p^2, t^2)  H-blurred
    __shared__ float  s_Hpt[IN_H * H_STRIDE];   // p*t         H-blurred
    __shared__ float s_warp[8];
    __shared__ int s_last;

    const int tid = threadIdx.x;
    const int ox = blockIdx.x * TX;
    const int oy = blockIdx.y * TY;
    const long plane_base = (long)blockIdx.z * (IMG * IMG);
    const float* __restrict__ p_plane = pred + plane_base;
    const float* __restrict__ t_plane = targ + plane_base;

    // packed weights (register-resident constants)
    u64 w2[11];
    #pragma unroll
    for (int k = 0; k < 11; k++) w2[k] = pk(Wt(k), Wt(k));

    // ---- Phase 0: load halo tile (zero padding) ----
    #pragma unroll 2
    for (int i = tid; i < IN_H * IN_W; i += NTHREADS) {
        int r = i / IN_W;
        int c = i - r * IN_W;
        int gy = oy + r - HALO;
        int gx = ox + c - HALO;
        float pv = 0.0f, tv = 0.0f;
        if ((unsigned)gy < IMG && (unsigned)gx < IMG) {
            int gi = gy * IMG + gx;
            pv = p_plane[gi];
            tv = t_plane[gi];
        }
        s_p[r * SP_STRIDE + c] = pv;
        s_t[r * SP_STRIDE + c] = tv;
    }
    __syncthreads();

    // ---- Phase 1: horizontal blur, packed chains ----
    for (int task = tid; task < IN_H * 8; task += NTHREADS) {
        int r = task >> 3;
        int c0 = (task & 7) * 4;
        const float* prow = &s_p[r * SP_STRIDE + c0];
        const float* trow = &s_t[r * SP_STRIDE + c0];

        float p[14], t[14];
        #pragma unroll
        for (int i = 0; i < 14; i++) { p[i] = prow[i]; t[i] = trow[i]; }

        const int hbase = r * H_STRIDE + c0;

        {   // mu = (p, t)
            u64 m[14];
            #pragma unroll
            for (int i = 0; i < 14; i++) m[i] = pk(p[i], t[i]);
            #pragma unroll
            for (int j = 0; j < 4; j++) {
                u64 a = 0ull;
                #pragma unroll
                for (int k = 0; k < 11; k++) a = fma2(w2[k], m[j + k], a);
                *(u64*)&s_Hmu[hbase + j] = a;
            }
        }
        {   // sq = (p*p, t*t)
            u64 m[14];
            #pragma unroll
            for (int i = 0; i < 14; i++) m[i] = pk(p[i] * p[i], t[i] * t[i]);
            #pragma unroll
            for (int j = 0; j < 4; j++) {
                u64 a = 0ull;
                #pragma unroll
                for (int k = 0; k < 11; k++) a = fma2(w2[k], m[j + k], a);
                *(u64*)&s_Hsq[hbase + j] = a;
            }
        }
        {   // pt = p*t (scalar, weight immediates -> FFMA-imm rt=1)
            float x[14];
            #pragma unroll
            for (int i = 0; i < 14; i++) x[i] = p[i] * t[i];
            #pragma unroll
            for (int j = 0; j < 4; j++) {
                float a = 0.f;
                #pragma unroll
                for (int k = 0; k < 11; k++) a = fmaf(Wt(k), x[j + k], a);
                s_Hpt[hbase + j] = a;
            }
        }
    }
    __syncthreads();

    // ---- Phase 2: vertical blur + SSIM (4 output rows per thread) ----
    const int x = tid & 31;
    const int y0 = (tid >> 5) * 4;

    u64 amu[4], asq[4];
    float apt[4];
    {
        u64 h[14];
        #pragma unroll
        for (int i = 0; i < 14; i++)
            h[i] = *(const u64*)&s_Hmu[(y0 + i) * H_STRIDE + x];
        #pragma unroll
        for (int j = 0; j < 4; j++) {
            u64 a = 0ull;
            #pragma unroll
            for (int k = 0; k < 11; k++) a = fma2(w2[k], h[j + k], a);
            amu[j] = a;
        }
    }
    {
        u64 h[14];
        #pragma unroll
        for (int i = 0; i < 14; i++)
            h[i] = *(const u64*)&s_Hsq[(y0 + i) * H_STRIDE + x];
        #pragma unroll
        for (int j = 0; j < 4; j++) {
            u64 a = 0ull;
            #pragma unroll
            for (int k = 0; k < 11; k++) a = fma2(w2[k], h[j + k], a);
            asq[j] = a;
        }
    }
    {
        float h[14];
        #pragma unroll
        for (int i = 0; i < 14; i++)
            h[i] = s_Hpt[(y0 + i) * H_STRIDE + x];
        #pragma unroll
        for (int j = 0; j < 4; j++) {
            float a = 0.f;
            #pragma unroll
            for (int k = 0; k < 11; k++) a = fmaf(Wt(k), h[j + k], a);
            apt[j] = a;
        }
    }

    float local = 0.0f;
    #pragma unroll
    for (int j = 0; j < 4; j++) {
        float2 mu = upk(amu[j]);
        float2 sq = upk(asq[j]);
        float mu_p = mu.x, mu_t = mu.y;
        float mu_p2 = mu_p * mu_p;
        float mu_t2 = mu_t * mu_t;
        float mu_pt = mu_p * mu_t;
        float num = (2.0f * mu_pt + C1) * (2.0f * (apt[j] - mu_pt) + C2);
        float den = (mu_p2 + mu_t2 + C1) *
                    ((sq.x - mu_p2) + (sq.y - mu_t2) + C2);
        local += __fdividef(num, den);
    }

    // ---- Phase 3: block reduction -> partial ----
    float v = local;
    #pragma unroll
    for (int off = 16; off; off >>= 1)
        v += __shfl_xor_sync(0xFFFFFFFFu, v, off);
    if ((tid & 31) == 0) s_warp[tid >> 5] = v;
    __syncthreads();
    if (tid < 8) {
        v = s_warp[tid];
        #pragma unroll
        for (int off = 4; off; off >>= 1)
            v += __shfl_xor_sync(0x000000FFu, v, off);
    }
    if (tid == 0) {
        int bl = (blockIdx.z * TILES_Y + blockIdx.y) * TILES_X + blockIdx.x;
        g_partials[bl] = v;
        __threadfence();
        unsigned t = atomicInc(&g_ticket, NBLOCKS - 1);  // wraps -> self-reset
        s_last = (t == NBLOCKS - 1);
    }
    __syncthreads();

    // ---- Phase 4: last block sums all partials (fixed order: deterministic) ----
    if (s_last) {
        float s = 0.0f;
        for (int i = tid; i < NBLOCKS; i += NTHREADS)
            s += __ldcg(&g_partials[i]);
        #pragma unroll
        for (int off = 16; off; off >>= 1)
            s += __shfl_xor_sync(0xFFFFFFFFu, s, off);
        if ((tid & 31) == 0) s_warp[tid >> 5] = s;
        __syncthreads();
        if (tid < 8) {
            s = s_warp[tid];
            #pragma unroll
            for (int off = 4; off; off >>= 1)
                s += __shfl_xor_sync(0x000000FFu, s, off);
            if (tid == 0) out[0] = 1.0f - s * (1.0f / NPIX);
        }
    }
}

extern "C" void kernel_launch(void* const* d_in, const int* in_sizes, int n_in,
                              void* d_out, int out_size) {
    const float* pred = (const float*)d_in[0];
    const float* targ = (const float*)d_in[1];
    float* out = (float*)d_out;

    dim3 grid(TILES_X, TILES_Y, PLANES);
    ssim_tile_kernel<<<grid, NTHREADS>>>(pred, targ, out);
}